// round 15
// baseline (speedup 1.0000x reference)
#include <cuda_runtime.h>
#include <cstdint>

// Single-launch 3-stage Tucker transform, cluster of 4 CTAs = one batch.
// Inter-stage exchange via st.shared::cluster into the consumer's K-major
// bf16-plane A tile. Round 14 (resubmit): cluster barriers split into
// arrive/wait with MMA + epilogue work slid between them (read-done hidden
// under ks=1 MMAs; write-done wait deferred to next stage top); mapa
// hoisted; final stage peeled.
//
// Stage GEMM: out[m,i] = sum_c A[m,c]*w[c,i]. A K-major: AT[c][m'], 32 rows
// x 256 bf16 per plane, fragments via ldmatrix.x4.trans.
// Granule swizzle: phys_gm = F(gm) ^ (k&7), F(gm)=((gm&3)<<3)|(gm>>2):
// ldmatrix reads, DSMEM column writes, and fill STS all conflict-free.
// Numerics (proven, rel_err 7.6e-6): bf16 two-plane split on mma m16n8k16,
// terms b0*B0 + b0*B1 + b1*B0.

#define PLANE_WORDS 4096           // 32 k-rows * 128 words (512 B/row)
#define PLANE_BYTES 16384
#define W_OFS       8192           // words: after single A buffer (2 planes)
#define SMEM_BYTES  ((W_OFS + 3 * 1280) * 4)   // 48128 B

__device__ __forceinline__ uint32_t packbf(float hi, float lo) {
    uint32_t r;
    asm("cvt.rn.bf16x2.f32 %0, %1, %2;" : "=r"(r) : "f"(hi), "f"(lo));
    return r;
}
__device__ __forceinline__ void split2(float vhi, float vlo, uint32_t& u, uint32_t& w) {
    u = packbf(vhi, vlo);
    float rlo = vlo - __uint_as_float(u << 16);
    float rhi = vhi - __uint_as_float(u & 0xFFFF0000u);
    w = packbf(rhi, rlo);
}
__device__ __forceinline__ void mma16(float* d, const uint32_t* a, uint32_t b0, uint32_t b1) {
    asm volatile(
        "mma.sync.aligned.m16n8k16.row.col.f32.bf16.bf16.f32 "
        "{%0,%1,%2,%3}, {%4,%5,%6,%7}, {%8,%9}, {%0,%1,%2,%3};"
        : "+f"(d[0]), "+f"(d[1]), "+f"(d[2]), "+f"(d[3])
        : "r"(a[0]), "r"(a[1]), "r"(a[2]), "r"(a[3]), "r"(b0), "r"(b1));
}
__device__ __forceinline__ void ldm4t(uint32_t* a, uint32_t saddr) {
    asm volatile("ldmatrix.sync.aligned.m8n8.x4.trans.shared.b16 {%0,%1,%2,%3}, [%4];"
        : "=r"(a[0]), "=r"(a[1]), "=r"(a[2]), "=r"(a[3]) : "r"(saddr));
}
__device__ __forceinline__ uint32_t Fgm(uint32_t gm) {
    return ((gm & 3u) << 3) | (gm >> 2);
}
__device__ __forceinline__ void stcluster(uint32_t addr, uint32_t v) {
    asm volatile("st.shared::cluster.b32 [%0], %1;" :: "r"(addr), "r"(v) : "memory");
}
__device__ __forceinline__ void carrive() {
    asm volatile("barrier.cluster.arrive.aligned;" ::: "memory");
}
__device__ __forceinline__ void cwait() {
    asm volatile("barrier.cluster.wait.aligned;" ::: "memory");
}

__global__ void __cluster_dims__(4, 1, 1) __launch_bounds__(256, 4)
tucker_dsmem(const float* __restrict__ x,
             const float* __restrict__ w0,
             const float* __restrict__ w1,
             const float* __restrict__ w2,
             float* __restrict__ out)
{
    extern __shared__ uint32_t smem[];

    const int tid  = threadIdx.x;
    const int wid  = tid >> 5;
    const int lane = tid & 31;
    const int g    = lane >> 2;
    const int tig  = lane & 3;

    const int rank = blockIdx.x & 3;
    const int b    = blockIdx.x >> 2;
    const int mb   = rank << 8;
    const long bb  = (long)b << 15;

    const uint32_t smemBase = (uint32_t)__cvta_generic_to_shared(smem);

    // ---- One-time weight prep: all 3 stages, two bf16x2 planes each. ----
    {
        const float* ws[3] = {w0, w1, w2};
        #pragma unroll
        for (int s3 = 0; s3 < 3; s3++) {
            uint32_t* Wp = smem + W_OFS + s3 * 1280;
            #pragma unroll
            for (int e = tid; e < 512; e += 256) {
                int n = e & 31, k2 = e >> 5;
                float lo = ws[s3][(2 * k2) * 32 + n];
                float hi = ws[s3][(2 * k2 + 1) * 32 + n];
                uint32_t pq, qq;
                split2(hi, lo, pq, qq);
                Wp[n * 20 + k2]       = pq;
                Wp[640 + n * 20 + k2] = qq;
            }
        }
    }

    // ---- Stage-0 fill: x is already K-major (row c = contiguous m). ----
    {
        #pragma unroll
        for (int rr = 0; rr < 4; rr++) {
            const int k = wid * 4 + rr;
            const float4* src = (const float4*)(x + bb + (long)k * 1024 + mb + lane * 8);
            float4 f0 = __ldcg(src);
            float4 f1 = __ldcg(src + 1);
            uint32_t p0[4], p1[4];
            split2(f0.y, f0.x, p0[0], p1[0]);
            split2(f0.w, f0.z, p0[1], p1[1]);
            split2(f1.y, f1.x, p0[2], p1[2]);
            split2(f1.w, f1.z, p0[3], p1[3]);
            uint32_t wofs = k * 128 + (Fgm(lane) ^ (k & 7)) * 4;
            *(uint4*)&smem[wofs]               = make_uint4(p0[0], p0[1], p0[2], p0[3]);
            *(uint4*)&smem[wofs + PLANE_WORDS] = make_uint4(p1[0], p1[1], p1[2], p1[3]);
        }
    }
    __syncthreads();

    // ---- Hoisted cluster-peer addresses (single A buffer => constant). ----
    const int cp = 8 * rank + wid;            // column this warp produces
    uint32_t remA[4];
    {
        const uint32_t locPlane0 = smemBase + cp * 512;
        #pragma unroll
        for (int pc = 0; pc < 4; pc++)
            asm("mapa.shared::cluster.u32 %0, %1, %2;"
                : "=r"(remA[pc]) : "r"(locPlane0), "r"(pc));
    }

    // Fragment addressing (constant across stages).
    const int klL = ((lane >> 4) << 3) + (lane & 7);         // k within k16
    const int gmL = 4 * wid + ((lane >> 3) & 1);             // gm base (st adds 2)

    // ================= Stages 0,1: DSMEM boundary =================
    #pragma unroll 1
    for (int s = 0; s < 2; s++) {
        const uint32_t* Wb0 = smem + W_OFS + s * 1280;
        const uint32_t* Wb1 = Wb0 + 640;

        if (s) cwait();                       // write-done of prev boundary

        float acc[2][4][4];
        #pragma unroll
        for (int a = 0; a < 2; a++)
            #pragma unroll
            for (int n = 0; n < 4; n++)
                #pragma unroll
                for (int q = 0; q < 4; q++)
                    acc[a][n][q] = 0.0f;

        #pragma unroll
        for (int ks = 0; ks < 2; ks++) {
            uint32_t ua[2][4], va[2][4];
            #pragma unroll
            for (int st = 0; st < 2; st++) {
                int klane = ks * 16 + klL;
                int gm    = gmL + 2 * st;
                uint32_t boff = klane * 512 + (Fgm(gm) ^ (klane & 7)) * 16;
                ldm4t(ua[st], smemBase + boff);
                ldm4t(va[st], smemBase + PLANE_BYTES + boff);
            }
            if (ks == 1) carrive();           // read-done: all A reads issued
            #pragma unroll
            for (int nt = 0; nt < 4; nt++) {
                int wo = (nt * 8 + g) * 20 + (ks << 3) + tig;
                uint32_t b00 = Wb0[wo], b01 = Wb0[wo + 4];
                uint32_t b10 = Wb1[wo], b11 = Wb1[wo + 4];
                mma16(acc[0][nt], ua[0], b00, b01);   // b0*B0
                mma16(acc[1][nt], ua[1], b00, b01);
                mma16(acc[0][nt], ua[0], b10, b11);   // b0*B1
                mma16(acc[1][nt], ua[1], b10, b11);
                mma16(acc[0][nt], va[0], b00, b01);   // b1*B0
                mma16(acc[1][nt], va[1], b00, b01);
            }
        }

        cwait();                              // read-done: peers finished reads

        // ---- DSMEM epilogue: warp owns column c' = cp. ----
        #pragma unroll
        for (int pc = 0; pc < 4; pc++) {
            const int st = pc >> 1, mh = pc & 1;
            #pragma unroll
            for (int nt = 0; nt < 4; nt++) {
                uint32_t u, v;
                split2(acc[st][nt][2 * mh + 1], acc[st][nt][2 * mh], u, v);
                uint32_t gmw = 4 * g + nt;
                uint32_t off = (Fgm(gmw) ^ (cp & 7)) * 16 + tig * 4;
                stcluster(remA[pc] + off, u);
                stcluster(remA[pc] + off + PLANE_BYTES, v);
            }
        }
        carrive();                            // write-done arrive (wait at next top)
    }

    // ================= Stage 2: gmem epilogue =================
    {
        const uint32_t* Wb0 = smem + W_OFS + 2 * 1280;
        const uint32_t* Wb1 = Wb0 + 640;

        cwait();                              // write-done of boundary 1

        float acc[2][4][4];
        #pragma unroll
        for (int a = 0; a < 2; a++)
            #pragma unroll
            for (int n = 0; n < 4; n++)
                #pragma unroll
                for (int q = 0; q < 4; q++)
                    acc[a][n][q] = 0.0f;

        #pragma unroll
        for (int ks = 0; ks < 2; ks++) {
            uint32_t ua[2][4], va[2][4];
            #pragma unroll
            for (int st = 0; st < 2; st++) {
                int klane = ks * 16 + klL;
                int gm    = gmL + 2 * st;
                uint32_t boff = klane * 512 + (Fgm(gm) ^ (klane & 7)) * 16;
                ldm4t(ua[st], smemBase + boff);
                ldm4t(va[st], smemBase + PLANE_BYTES + boff);
            }
            #pragma unroll
            for (int nt = 0; nt < 4; nt++) {
                int wo = (nt * 8 + g) * 20 + (ks << 3) + tig;
                uint32_t b00 = Wb0[wo], b01 = Wb0[wo + 4];
                uint32_t b10 = Wb1[wo], b11 = Wb1[wo + 4];
                mma16(acc[0][nt], ua[0], b00, b01);
                mma16(acc[1][nt], ua[1], b00, b01);
                mma16(acc[0][nt], ua[0], b10, b11);
                mma16(acc[1][nt], ua[1], b10, b11);
                mma16(acc[0][nt], va[0], b00, b01);
                mma16(acc[1][nt], va[1], b00, b01);
            }
        }

        float* ob = out + bb + (long)mb * 32;
        #pragma unroll
        for (int st = 0; st < 2; st++) {
            int m0 = (wid << 5) + (st << 4) + g;
            int m1 = m0 + 8;
            #pragma unroll
            for (int nt = 0; nt < 4; nt++) {
                int i0 = (nt << 3) + (tig << 1);
                __stwt((float2*)&ob[(m0 << 5) + i0],
                       make_float2(acc[st][nt][0], acc[st][nt][1]));
                __stwt((float2*)&ob[(m1 << 5) + i0],
                       make_float2(acc[st][nt][2], acc[st][nt][3]));
            }
        }
    }
}

extern "C" void kernel_launch(void* const* d_in, const int* in_sizes, int n_in,
                              void* d_out, int out_size)
{
    const float* x  = (const float*)d_in[0];
    const float* w0 = (const float*)d_in[1];
    const float* w1 = (const float*)d_in[2];
    const float* w2 = (const float*)d_in[3];
    float* out = (float*)d_out;

    const int nBatch = in_sizes[0] >> 15;
    const int grid = nBatch * 4;            // cluster (4,1,1) per batch

    cudaFuncSetAttribute(tucker_dsmem,
                         cudaFuncAttributeMaxDynamicSharedMemorySize, SMEM_BYTES);
    tucker_dsmem<<<grid, 256, SMEM_BYTES>>>(x, w0, w1, w2, out);
}

// round 16
// speedup vs baseline: 1.1439x; 1.1439x over previous
#include <cuda_runtime.h>
#include <cstdint>

// Single-launch 3-stage Tucker transform, cluster of 4 CTAs = one batch.
// Inter-stage exchange via st.shared::cluster into the consumer's K-major
// bf16-plane A tile (no gmem round trip). Structure = Round 13 (validated
// 133.7us): single A buffer, fused read-done/write-done cluster barriers,
// hoisted all-stage weight prep, launch_bounds(256,4), unified stage loop.
// Round 16 delta: stage-0 fill LDGs issued FIRST so their DRAM latency
// overlaps the weight-prep work.
//
// Stage GEMM: out[m,i] = sum_c A[m,c]*w[c,i]. A K-major: AT[c][m'], 32 rows
// x 256 bf16 per plane, fragments via ldmatrix.x4.trans.
// Granule swizzle: phys_gm = F(gm) ^ (k&7), F(gm)=((gm&3)<<3)|(gm>>2):
// ldmatrix reads, DSMEM column writes, and fill STS all conflict-free.
// Numerics (proven, rel_err 7.6e-6): bf16 two-plane split on mma m16n8k16,
// terms b0*B0 + b0*B1 + b1*B0.

#define PLANE_WORDS 4096           // 32 k-rows * 128 words (512 B/row)
#define PLANE_BYTES 16384
#define W_OFS       8192           // words: after single A buffer (2 planes)
#define SMEM_BYTES  ((W_OFS + 3 * 1280) * 4)   // 48128 B

__device__ __forceinline__ uint32_t packbf(float hi, float lo) {
    uint32_t r;
    asm("cvt.rn.bf16x2.f32 %0, %1, %2;" : "=r"(r) : "f"(hi), "f"(lo));
    return r;
}
__device__ __forceinline__ void split2(float vhi, float vlo, uint32_t& u, uint32_t& w) {
    u = packbf(vhi, vlo);
    float rlo = vlo - __uint_as_float(u << 16);
    float rhi = vhi - __uint_as_float(u & 0xFFFF0000u);
    w = packbf(rhi, rlo);
}
__device__ __forceinline__ void mma16(float* d, const uint32_t* a, uint32_t b0, uint32_t b1) {
    asm volatile(
        "mma.sync.aligned.m16n8k16.row.col.f32.bf16.bf16.f32 "
        "{%0,%1,%2,%3}, {%4,%5,%6,%7}, {%8,%9}, {%0,%1,%2,%3};"
        : "+f"(d[0]), "+f"(d[1]), "+f"(d[2]), "+f"(d[3])
        : "r"(a[0]), "r"(a[1]), "r"(a[2]), "r"(a[3]), "r"(b0), "r"(b1));
}
__device__ __forceinline__ void ldm4t(uint32_t* a, uint32_t saddr) {
    asm volatile("ldmatrix.sync.aligned.m8n8.x4.trans.shared.b16 {%0,%1,%2,%3}, [%4];"
        : "=r"(a[0]), "=r"(a[1]), "=r"(a[2]), "=r"(a[3]) : "r"(saddr));
}
__device__ __forceinline__ uint32_t Fgm(uint32_t gm) {
    return ((gm & 3u) << 3) | (gm >> 2);
}
__device__ __forceinline__ void stcluster(uint32_t addr, uint32_t v) {
    asm volatile("st.shared::cluster.b32 [%0], %1;" :: "r"(addr), "r"(v) : "memory");
}
__device__ __forceinline__ void cbar() {
    asm volatile("barrier.cluster.arrive.aligned;" ::: "memory");
    asm volatile("barrier.cluster.wait.aligned;" ::: "memory");
}

__global__ void __cluster_dims__(4, 1, 1) __launch_bounds__(256, 4)
tucker_dsmem(const float* __restrict__ x,
             const float* __restrict__ w0,
             const float* __restrict__ w1,
             const float* __restrict__ w2,
             float* __restrict__ out)
{
    extern __shared__ uint32_t smem[];

    const int tid  = threadIdx.x;
    const int wid  = tid >> 5;
    const int lane = tid & 31;
    const int g    = lane >> 2;
    const int tig  = lane & 3;

    const int rank = blockIdx.x & 3;
    const int b    = blockIdx.x >> 2;
    const int mb   = rank << 8;
    const long bb  = (long)b << 15;

    const uint32_t smemBase = (uint32_t)__cvta_generic_to_shared(smem);

    // ---- Round 16: issue stage-0 fill loads FIRST (x is K-major). ----
    float4 f[4][2];
    #pragma unroll
    for (int rr = 0; rr < 4; rr++) {
        const int k = wid * 4 + rr;
        const float4* src = (const float4*)(x + bb + (long)k * 1024 + mb + lane * 8);
        f[rr][0] = __ldcg(src);
        f[rr][1] = __ldcg(src + 1);
    }

    // ---- Weight prep (overlaps fill-load latency): 3 stages, 2 planes. ----
    {
        const float* ws[3] = {w0, w1, w2};
        #pragma unroll
        for (int s3 = 0; s3 < 3; s3++) {
            uint32_t* Wp = smem + W_OFS + s3 * 1280;
            #pragma unroll
            for (int e = tid; e < 512; e += 256) {
                int n = e & 31, k2 = e >> 5;
                float lo = ws[s3][(2 * k2) * 32 + n];
                float hi = ws[s3][(2 * k2 + 1) * 32 + n];
                uint32_t pq, qq;
                split2(hi, lo, pq, qq);
                Wp[n * 20 + k2]       = pq;
                Wp[640 + n * 20 + k2] = qq;
            }
        }
    }

    // ---- Consume fill loads: split fp32 -> two bf16 planes, STS. ----
    {
        #pragma unroll
        for (int rr = 0; rr < 4; rr++) {
            const int k = wid * 4 + rr;
            uint32_t p0[4], p1[4];
            split2(f[rr][0].y, f[rr][0].x, p0[0], p1[0]);
            split2(f[rr][0].w, f[rr][0].z, p0[1], p1[1]);
            split2(f[rr][1].y, f[rr][1].x, p0[2], p1[2]);
            split2(f[rr][1].w, f[rr][1].z, p0[3], p1[3]);
            uint32_t wofs = k * 128 + (Fgm(lane) ^ (k & 7)) * 4;
            *(uint4*)&smem[wofs]               = make_uint4(p0[0], p0[1], p0[2], p0[3]);
            *(uint4*)&smem[wofs + PLANE_WORDS] = make_uint4(p1[0], p1[1], p1[2], p1[3]);
        }
    }
    __syncthreads();

    #pragma unroll 1
    for (int s = 0; s < 3; s++) {
        const uint32_t* Wb0 = smem + W_OFS + s * 1280;
        const uint32_t* Wb1 = Wb0 + 640;

        // ---- Mainloop: ldmatrix.trans fragments from K-major A planes. ----
        float acc[2][4][4];
        #pragma unroll
        for (int a = 0; a < 2; a++)
            #pragma unroll
            for (int n = 0; n < 4; n++)
                #pragma unroll
                for (int q = 0; q < 4; q++)
                    acc[a][n][q] = 0.0f;

        #pragma unroll
        for (int ks = 0; ks < 2; ks++) {
            uint32_t ua[2][4], va[2][4];
            #pragma unroll
            for (int st = 0; st < 2; st++) {
                int klane = ks * 16 + ((lane >> 4) << 3) + (lane & 7);
                int gm    = 4 * wid + 2 * st + ((lane >> 3) & 1);
                uint32_t boff = klane * 512 + (Fgm(gm) ^ (klane & 7)) * 16;
                ldm4t(ua[st], smemBase + boff);
                ldm4t(va[st], smemBase + PLANE_BYTES + boff);
            }
            #pragma unroll
            for (int nt = 0; nt < 4; nt++) {
                int wo = (nt * 8 + g) * 20 + (ks << 3) + tig;
                uint32_t b00 = Wb0[wo], b01 = Wb0[wo + 4];
                uint32_t b10 = Wb1[wo], b11 = Wb1[wo + 4];
                mma16(acc[0][nt], ua[0], b00, b01);   // b0*B0
                mma16(acc[1][nt], ua[1], b00, b01);
                mma16(acc[0][nt], ua[0], b10, b11);   // b0*B1
                mma16(acc[1][nt], ua[1], b10, b11);
                mma16(acc[0][nt], va[0], b00, b01);   // b1*B0
                mma16(acc[1][nt], va[1], b00, b01);
            }
        }

        if (s < 2) {
            // Read-done: no peer may overwrite the (single) A buffer until
            // every cluster CTA finished its mainloop reads.
            cbar();

            // ---- DSMEM epilogue: warp owns column c' = 8*rank + wid. ----
            const int cp = 8 * rank + wid;
            const uint32_t locPlane0 = smemBase + cp * 512;
            #pragma unroll
            for (int pc = 0; pc < 4; pc++) {
                uint32_t rem;
                asm("mapa.shared::cluster.u32 %0, %1, %2;"
                    : "=r"(rem) : "r"(locPlane0), "r"(pc));
                const int st = pc >> 1, mh = pc & 1;
                #pragma unroll
                for (int nt = 0; nt < 4; nt++) {
                    uint32_t u, v;
                    split2(acc[st][nt][2 * mh + 1], acc[st][nt][2 * mh], u, v);
                    uint32_t gmw = 4 * g + nt;
                    uint32_t off = (Fgm(gmw) ^ (cp & 7)) * 16 + tig * 4;
                    stcluster(rem + off, u);
                    stcluster(rem + off + PLANE_BYTES, v);
                }
            }
            // Write-done: peers' tiles fully written before next mainloop.
            cbar();
        } else {
            // ---- Final stage: stream to gmem, out flat = (mb+m)*32 + i. ----
            float* ob = out + bb + (long)mb * 32;
            #pragma unroll
            for (int st = 0; st < 2; st++) {
                int m0 = (wid << 5) + (st << 4) + g;
                int m1 = m0 + 8;
                #pragma unroll
                for (int nt = 0; nt < 4; nt++) {
                    int i0 = (nt << 3) + (tig << 1);
                    __stwt((float2*)&ob[(m0 << 5) + i0],
                           make_float2(acc[st][nt][0], acc[st][nt][1]));
                    __stwt((float2*)&ob[(m1 << 5) + i0],
                           make_float2(acc[st][nt][2], acc[st][nt][3]));
                }
            }
        }
    }
}

extern "C" void kernel_launch(void* const* d_in, const int* in_sizes, int n_in,
                              void* d_out, int out_size)
{
    const float* x  = (const float*)d_in[0];
    const float* w0 = (const float*)d_in[1];
    const float* w1 = (const float*)d_in[2];
    const float* w2 = (const float*)d_in[3];
    float* out = (float*)d_out;

    const int nBatch = in_sizes[0] >> 15;
    const int grid = nBatch * 4;            // cluster (4,1,1) per batch

    cudaFuncSetAttribute(tucker_dsmem,
                         cudaFuncAttributeMaxDynamicSharedMemorySize, SMEM_BYTES);
    tucker_dsmem<<<grid, 256, SMEM_BYTES>>>(x, w0, w1, w2, out);
}